// round 16
// baseline (speedup 1.0000x reference)
#include <cuda_runtime.h>
#include <cuda_fp16.h>
#include <math.h>
#include <stdint.h>

// IAF, 2 MADE flows, B=4096, D=H=64.
// Identity (verified R1/R4-R15): the reference forward scan is the exact
// inverse of z -> z - shift(z), so density = -0.5*D*log(2pi) - 0.5*sum(lv)
// - 0.5*sum(eps^2); only the inverse pass (8 masked [Bx64]@[64x64] GEMMs) runs.
// R16: activation buffer stored tig-major-permuted so each lane's A-fragment
// is 2x LDS.128 per row (4 total/layer, conflict-free w/ stride 36) instead
// of 16 LDS.32. Epilogue STS accepts a 4-way bank conflict (proven
// unavoidable jointly). Rest frozen from R15: fp16 m16n8k16 MMA, 16 warps =
// 2 tiles x 8 n-blocks, tile barriers, folded reversal, LDG-first staging.

#define C_DENS (-58.81206612509905f)
#define AST  68                // fp32 z row stride (floats)
#define ASTH 36                // activation row stride (half2 units)
#define NSTW 72                // weight row stride (half2 units)
#define WMAT (32 * NSTW)       // half2 per staged matrix (2304)

static __device__ __forceinline__ void mma16(float* d, uint32_t a0, uint32_t a1,
                                             uint32_t a2, uint32_t a3,
                                             uint32_t b0, uint32_t b1) {
    asm volatile(
        "mma.sync.aligned.m16n8k16.row.col.f32.f16.f16.f32 "
        "{%0,%1,%2,%3}, {%4,%5,%6,%7}, {%8,%9}, {%0,%1,%2,%3};"
        : "+f"(d[0]), "+f"(d[1]), "+f"(d[2]), "+f"(d[3])
        : "r"(a0), "r"(a1), "r"(a2), "r"(a3), "r"(b0), "r"(b1));
}

static __device__ __forceinline__ void tile_bar(int p) {
    asm volatile("bar.sync %0, 256;" :: "r"(p + 1) : "memory");
}

static __device__ __forceinline__ uint32_t h2swap(uint32_t v) {
    return __byte_perm(v, 0, 0x1032);       // swap fp16 halves
}

static __device__ __forceinline__ uint32_t f2h2(float lo, float hi) {
    __half2 h = __floats2half2_rn(lo, hi);
    return *reinterpret_cast<uint32_t*>(&h);
}

// Permuted position of half2 column-pair j (cols 2j, 2j+1) within an act row:
// j = [kb:2][s:1][tig:2]  ->  pos = tig*8 + kb*2 + s   (tig-major blocks)
// Lane (g,tig) A-fragment = positions tig*8 .. tig*8+7  ->  2x uint4.

__global__ __launch_bounds__(512, 1)
void iaf_main(const float* __restrict__ zm, const float* __restrict__ lv,
              const float* __restrict__ ep,
              const float* __restrict__ W0, const float* __restrict__ b0,
              const float* __restrict__ W1, const float* __restrict__ b1,
              const float* __restrict__ W2, const float* __restrict__ b2,
              const float* __restrict__ Wo, const float* __restrict__ bo,
              float* __restrict__ out, int B)
{
    extern __shared__ float sm[];
    uint32_t* wsm2 = (uint32_t*)sm;           // [8][32 kpair][NSTW] half2 weights
    uint32_t* abuf = wsm2 + 8 * WMAT;         // [2][2][16][ASTH] permuted acts
    float*    zb   = (float*)(abuf + 2 * 2 * 16 * ASTH);  // [2][16][AST] fp32 z

    const int t = threadIdx.x;
    const int lane = t & 31, wid = t >> 5;
    const int p = wid >> 3, h = wid & 7;      // tile, n-block (8 cols)
    const int g = lane >> 2, tig = lane & 3;
    const int rowbase = blockIdx.x * 32 + p * 16;
    const int n = h * 8 + g;                  // this lane's weight column
    const int c = 8 * h + 2 * tig;            // this lane's output column pair
    const int posw = tig * 8 + (h >> 1) * 2 + (h & 1);   // epilogue act pos

    // ---- Issue ALL weight LDGs first; latency overlaps init below.
    float4 wa[8], wb[8];
    #pragma unroll
    for (int it = 0; it < 8; ++it) {
        int i   = t + it * 512;               // 0..4095
        int mat = i >> 9;
        int f = mat >> 2, l = mat & 3;
        int rem = i & 511;
        int kp  = rem >> 4;
        int n0  = (rem & 15) << 2;
        const float* src = (l == 0) ? W0 : (l == 1) ? W1 : (l == 2) ? W2 : Wo;
        src += f * 4096 + (kp << 7) + n0;     // row 2kp
        wa[it] = *(const float4*)(src);
        wb[it] = *(const float4*)(src + 64);  // row 2kp+1
    }

    // Biases (fp32) for this lane's columns, all 8 layers (exec order).
    float2 biasr[8];
    {
        const float* Bseq[8] = { b0 + 64, b1 + 64, b2 + 64, bo + 64,
                                 b0,      b1,      b2,      bo      };
        #pragma unroll
        for (int i = 0; i < 8; ++i)
            biasr[i] = *(const float2*)(Bseq[i] + c);
    }

    // ---- Init: z0 = zm + exp(0.5*lv)*eps; density; acts fp16 (permuted).
    {
        int r = t >> 4, seg = t & 15;         // 32 rows x 16 col-segments
        int pi = r >> 4, ri = r & 15;
        int gr = blockIdx.x * 32 + r;
        bool v = gr < B;
        int col = seg * 4;
        const size_t go = (size_t)gr * 64 + col;
        float4 a = v ? *(const float4*)(zm + go) : make_float4(0,0,0,0);
        float4 b = v ? *(const float4*)(lv + go) : make_float4(0,0,0,0);
        float4 cc = v ? *(const float4*)(ep + go) : make_float4(0,0,0,0);
        float4 z4;
        z4.x = a.x + __expf(0.5f * b.x) * cc.x;
        z4.y = a.y + __expf(0.5f * b.y) * cc.y;
        z4.z = a.z + __expf(0.5f * b.z) * cc.z;
        z4.w = a.w + __expf(0.5f * b.w) * cc.w;
        *(float4*)(zb + (pi * 16 + ri) * AST + col) = z4;
        // Column-pairs j0 = 2seg (pos0), j1 = 2seg+1 (pos0+8).
        int pos0 = 16 * (seg & 1) + 2 * (seg >> 2) + ((seg >> 1) & 1);
        uint32_t* arow = abuf + ((0 * 2 + pi) * 16 + ri) * ASTH;
        arow[pos0]     = f2h2(z4.x, z4.y);
        arow[pos0 + 8] = f2h2(z4.z, z4.w);
        float slv = b.x + b.y + b.z + b.w;
        float se2 = cc.x*cc.x + cc.y*cc.y + cc.z*cc.z + cc.w*cc.w;
        #pragma unroll
        for (int m = 1; m <= 8; m <<= 1) {
            slv += __shfl_xor_sync(0xffffffffu, slv, m);
            se2 += __shfl_xor_sync(0xffffffffu, se2, m);
        }
        if (seg == 0 && v)
            out[(size_t)B * 64 + gr] = C_DENS - 0.5f * slv - 0.5f * se2;
    }

    // ---- Mask + cvt fp16 + k-pack + store staged weights (thread-local).
    #pragma unroll
    for (int it = 0; it < 8; ++it) {
        int i   = t + it * 512;
        int mat = i >> 9;
        int l   = mat & 3;
        int rem = i & 511;
        int kp  = rem >> 4;
        int n0  = (rem & 15) << 2;
        int k0  = kp << 1;
        int k1  = k0 + 1;
        int k1m = (k1 == 63) ? 0 : k1;
        float va[4] = {wa[it].x, wa[it].y, wa[it].z, wa[it].w};
        float vb[4] = {wb[it].x, wb[it].y, wb[it].z, wb[it].w};
        uint4 r;
        uint32_t* rp = &r.x;
        #pragma unroll
        for (int q = 0; q < 4; ++q) {
            int nn = n0 + q;
            int nm = (nn == 63) ? 0 : nn;
            bool ka = (l == 0) ? (k0 <= nm)
                    : (l == 3) ? (k0 < nn)
                               : (k0 <= nm);
            bool kb2 = (l == 0) ? (k1 <= nm)
                     : (l == 3) ? (k1m < nn)
                                : (k1m <= nm);
            rp[q] = f2h2(ka ? va[q] : 0.0f, kb2 ? vb[q] : 0.0f);
        }
        *(uint4*)(wsm2 + (mat * 32 + kp) * NSTW + n0) = r;
    }
    __syncthreads();

    float* zrow0 = zb + (p * 16 + g) * AST;
    float* zrow1 = zb + (p * 16 + g + 8) * AST;

    // Prefetch layer-0 B-fragments (mat exec order: 4,5,6,7,0,1,2,3).
    uint32_t Bc0[4], Bc1[4], Bn0[4], Bn1[4];
    {
        const uint32_t* wbp = wsm2 + 4 * WMAT + n;
        #pragma unroll
        for (int kb = 0; kb < 4; ++kb) {
            Bc0[kb] = wbp[(kb * 8 + tig) * NSTW];
            Bc1[kb] = wbp[(kb * 8 + tig + 4) * NSTW];
        }
    }

    // ---- 8 chained layers, fully unrolled; tile-scoped barriers.
    #pragma unroll
    for (int li = 0; li < 8; ++li) {
        const int l  = ((li < 4) ? (4 + li) : (li - 4)) & 3;
        const int rd = li & 1, wr = (li + 1) & 1;

        // Prefetch next layer's B-fragments (conflict-free, overlaps MMAs).
        if (li < 7) {
            const int nmat = (li < 3) ? (5 + li) : (li - 3);
            const uint32_t* wbp = wsm2 + nmat * WMAT + n;
            #pragma unroll
            for (int kb = 0; kb < 4; ++kb) {
                Bn0[kb] = wbp[(kb * 8 + tig) * NSTW];
                Bn1[kb] = wbp[(kb * 8 + tig + 4) * NSTW];
            }
        }

        // A-fragments: 2x uint4 per row, conflict-free (banks tile 0..31).
        const uint32_t* ar0 = abuf + ((rd * 2 + p) * 16 + g) * ASTH;
        const uint32_t* ar1 = ar0 + 8 * ASTH;
        uint32_t A0[4], A1[4], A2[4], A3[4];
        if (li != 4) {
            uint4 q0 = *(const uint4*)(ar0 + tig * 8);
            uint4 q1 = *(const uint4*)(ar0 + tig * 8 + 4);
            uint4 r0 = *(const uint4*)(ar1 + tig * 8);
            uint4 r1 = *(const uint4*)(ar1 + tig * 8 + 4);
            A0[0]=q0.x; A2[0]=q0.y; A0[1]=q0.z; A2[1]=q0.w;
            A0[2]=q1.x; A2[2]=q1.y; A0[3]=q1.z; A2[3]=q1.w;
            A1[0]=r0.x; A3[0]=r0.y; A1[1]=r0.z; A3[1]=r0.w;
            A1[2]=r1.x; A3[2]=r1.y; A1[3]=r1.z; A3[3]=r1.w;
        } else {
            // Reversal: v[pair j] = h2swap(u[pair 31-j]); base (3-tig)*8.
            const int rb = (3 - tig) * 8;
            uint4 q0 = *(const uint4*)(ar0 + rb);
            uint4 q1 = *(const uint4*)(ar0 + rb + 4);
            uint4 r0 = *(const uint4*)(ar1 + rb);
            uint4 r1 = *(const uint4*)(ar1 + rb + 4);
            A0[3]=h2swap(q0.y); A2[3]=h2swap(q0.x);
            A0[2]=h2swap(q0.w); A2[2]=h2swap(q0.z);
            A0[1]=h2swap(q1.y); A2[1]=h2swap(q1.x);
            A0[0]=h2swap(q1.w); A2[0]=h2swap(q1.z);
            A1[3]=h2swap(r0.y); A3[3]=h2swap(r0.x);
            A1[2]=h2swap(r0.w); A3[2]=h2swap(r0.z);
            A1[1]=h2swap(r1.y); A3[1]=h2swap(r1.x);
            A1[0]=h2swap(r1.w); A3[0]=h2swap(r1.z);
        }

        // Dual accumulator chains, merged at the end.
        float accA[4] = {0.f, 0.f, 0.f, 0.f};
        float accB[4] = {0.f, 0.f, 0.f, 0.f};
        mma16(accA, A0[0], A1[0], A2[0], A3[0], Bc0[0], Bc1[0]);
        mma16(accA, A0[1], A1[1], A2[1], A3[1], Bc0[1], Bc1[1]);
        mma16(accB, A0[2], A1[2], A2[2], A3[2], Bc0[2], Bc1[2]);
        mma16(accB, A0[3], A1[3], A2[3], A3[3], Bc0[3], Bc1[3]);
        float acc[4];
        #pragma unroll
        for (int i = 0; i < 4; ++i) acc[i] = accA[i] + accB[i];

        const float2 bias = biasr[li];
        uint32_t* aw0 = abuf + ((wr * 2 + p) * 16 + g) * ASTH;
        uint32_t* aw1 = aw0 + 8 * ASTH;

        if (l < 3) {
            float v0 = fmaxf(acc[0] + bias.x, 0.f);
            float v1 = fmaxf(acc[1] + bias.y, 0.f);
            float v2 = fmaxf(acc[2] + bias.x, 0.f);
            float v3 = fmaxf(acc[3] + bias.y, 0.f);
            aw0[posw] = f2h2(v0, v1);
            aw1[posw] = f2h2(v2, v3);
            tile_bar(p);
        } else if (li == 3) {
            // u = z - shift_1(z); exact fp32 to zb, fp16 to act buffer.
            float2 z0 = *(const float2*)(zrow0 + c);
            float2 z1 = *(const float2*)(zrow1 + c);
            float u0 = z0.x - (acc[0] + bias.x);
            float u1 = z0.y - (acc[1] + bias.y);
            float u2 = z1.x - (acc[2] + bias.x);
            float u3 = z1.y - (acc[3] + bias.y);
            aw0[posw] = f2h2(u0, u1);
            aw1[posw] = f2h2(u2, u3);
            *(float2*)(zrow0 + c) = make_float2(u0, u1);
            *(float2*)(zrow1 + c) = make_float2(u2, u3);
            tile_bar(p);
        } else {
            // Final: out[c] = v[c] - shift_0(v)[c], v[c] = u[63-c] (fp32 zb).
            float2 zr0 = *(const float2*)(zrow0 + 62 - c);  // (u[62-c], u[63-c])
            float2 zr1 = *(const float2*)(zrow1 + 62 - c);
            float zn0 = zr0.y - (acc[0] + bias.x);
            float zn1 = zr0.x - (acc[1] + bias.y);
            float zn2 = zr1.y - (acc[2] + bias.x);
            float zn3 = zr1.x - (acc[3] + bias.y);
            const int r0 = rowbase + g, r1 = r0 + 8;
            if (r0 < B)
                *(float2*)(out + (size_t)r0*64 + c) = make_float2(zn0, zn1);
            if (r1 < B)
                *(float2*)(out + (size_t)r1*64 + c) = make_float2(zn2, zn3);
        }

        // Rotate prefetch buffers (register renames under full unroll).
        #pragma unroll
        for (int i = 0; i < 4; ++i) { Bc0[i] = Bn0[i]; Bc1[i] = Bn1[i]; }
    }
}

extern "C" void kernel_launch(void* const* d_in, const int* in_sizes, int n_in,
                              void* d_out, int out_size) {
    const float* zm = (const float*)d_in[0];
    const float* lv = (const float*)d_in[1];
    const float* ep = (const float*)d_in[2];
    const float* W0 = (const float*)d_in[3];
    const float* b0 = (const float*)d_in[4];
    const float* W1 = (const float*)d_in[5];
    const float* b1 = (const float*)d_in[6];
    const float* W2 = (const float*)d_in[7];
    const float* b2 = (const float*)d_in[8];
    const float* Wo = (const float*)d_in[9];
    const float* bo = (const float*)d_in[10];

    int B = in_sizes[0] / 64;

    int smem = (8 * WMAT + 2 * 2 * 16 * ASTH) * 4 + 2 * 16 * AST * 4;  // 91648
    cudaFuncSetAttribute(iaf_main, cudaFuncAttributeMaxDynamicSharedMemorySize,
                         smem);
    int grid = (B + 31) / 32;
    iaf_main<<<grid, 512, smem>>>(zm, lv, ep, W0, b0, W1, b1, W2, b2, Wo, bo,
                                  (float*)d_out, B);
}

// round 17
// speedup vs baseline: 1.0191x; 1.0191x over previous
#include <cuda_runtime.h>
#include <cuda_fp16.h>
#include <math.h>
#include <stdint.h>

// IAF, 2 MADE flows, B=4096, D=H=64.
// Identity (verified R1/R4-R16): the reference forward scan is the exact
// inverse of z -> z - shift(z), so density = -0.5*D*log(2pi) - 0.5*sum(lv)
// - 0.5*sum(eps^2); only the inverse pass (8 masked [Bx64]@[64x64] GEMMs) runs.
// R17: split staging -- mats 4-7 (used by layers 0-3) staged before the sync,
// mats 0-3 staged AFTER it, overlapped with layers 0-3 compute; the block-wide
// barrier layer 3 already needs (__syncthreads) orders them before first use.
// 4 independent MMA accumulators (tree merge). Rest frozen from R15: fp16
// m16n8k16, 16 warps = 2 tiles x 8 n-blocks, tile barriers, folded reversal.

#define C_DENS (-58.81206612509905f)
#define AST  68                // fp32 z row stride (floats)
#define ASTH 36                // activation row stride (half2 units)
#define NSTW 72                // weight row stride (half2 units)
#define WMAT (32 * NSTW)       // half2 per staged matrix (2304)

static __device__ __forceinline__ void mma16(float* d, uint32_t a0, uint32_t a1,
                                             uint32_t a2, uint32_t a3,
                                             uint32_t b0, uint32_t b1) {
    asm volatile(
        "mma.sync.aligned.m16n8k16.row.col.f32.f16.f16.f32 "
        "{%0,%1,%2,%3}, {%4,%5,%6,%7}, {%8,%9}, {%0,%1,%2,%3};"
        : "+f"(d[0]), "+f"(d[1]), "+f"(d[2]), "+f"(d[3])
        : "r"(a0), "r"(a1), "r"(a2), "r"(a3), "r"(b0), "r"(b1));
}

static __device__ __forceinline__ void tile_bar(int p) {
    asm volatile("bar.sync %0, 256;" :: "r"(p + 1) : "memory");
}

static __device__ __forceinline__ uint32_t h2swap(uint32_t v) {
    return __byte_perm(v, 0, 0x1032);       // swap fp16 halves
}

static __device__ __forceinline__ uint32_t f2h2(float lo, float hi) {
    __half2 h = __floats2half2_rn(lo, hi);
    return *reinterpret_cast<uint32_t*>(&h);
}

__global__ __launch_bounds__(512, 1)
void iaf_main(const float* __restrict__ zm, const float* __restrict__ lv,
              const float* __restrict__ ep,
              const float* __restrict__ W0, const float* __restrict__ b0,
              const float* __restrict__ W1, const float* __restrict__ b1,
              const float* __restrict__ W2, const float* __restrict__ b2,
              const float* __restrict__ Wo, const float* __restrict__ bo,
              float* __restrict__ out, int B)
{
    extern __shared__ float sm[];
    uint32_t* wsm2 = (uint32_t*)sm;           // [8][32 kpair][NSTW] half2 weights
    uint32_t* abuf = wsm2 + 8 * WMAT;         // [2][2][16][ASTH] half2 acts
    float*    zb   = (float*)(abuf + 2 * 2 * 16 * ASTH);  // [2][16][AST] fp32 z

    const int t = threadIdx.x;
    const int lane = t & 31, wid = t >> 5;
    const int p = wid >> 3, h = wid & 7;      // tile, n-block (8 cols)
    const int g = lane >> 2, tig = lane & 3;
    const int rowbase = blockIdx.x * 32 + p * 16;
    const int n = h * 8 + g;                  // this lane's weight column
    const int c = 8 * h + 2 * tig;            // this lane's output column pair

    // ---- Issue ALL weight LDGs first; latency overlaps init below.
    // i = t + it*512: it=0..3 -> mats 0-3 (flow 0), it=4..7 -> mats 4-7.
    float4 wa[8], wb[8];
    #pragma unroll
    for (int it = 0; it < 8; ++it) {
        int i   = t + it * 512;               // 0..4095
        int mat = i >> 9;
        int f = mat >> 2, l = mat & 3;
        int rem = i & 511;
        int kp  = rem >> 4;
        int n0  = (rem & 15) << 2;
        const float* src = (l == 0) ? W0 : (l == 1) ? W1 : (l == 2) ? W2 : Wo;
        src += f * 4096 + (kp << 7) + n0;     // row 2kp
        wa[it] = *(const float4*)(src);
        wb[it] = *(const float4*)(src + 64);  // row 2kp+1
    }

    // Biases (fp32) for this lane's columns, all 8 layers (exec order).
    float2 biasr[8];
    {
        const float* Bseq[8] = { b0 + 64, b1 + 64, b2 + 64, bo + 64,
                                 b0,      b1,      b2,      bo      };
        #pragma unroll
        for (int i = 0; i < 8; ++i)
            biasr[i] = *(const float2*)(Bseq[i] + c);
    }

    // ---- Init: z0 = zm + exp(0.5*lv)*eps; density; acts fp16, z fp32.
    {
        int r = t >> 4, seg = t & 15;         // 32 rows x 16 col-segments
        int pi = r >> 4, ri = r & 15;
        int gr = blockIdx.x * 32 + r;
        bool v = gr < B;
        int col = seg * 4;
        const size_t go = (size_t)gr * 64 + col;
        float4 a = v ? *(const float4*)(zm + go) : make_float4(0,0,0,0);
        float4 b = v ? *(const float4*)(lv + go) : make_float4(0,0,0,0);
        float4 cc = v ? *(const float4*)(ep + go) : make_float4(0,0,0,0);
        float4 z4;
        z4.x = a.x + __expf(0.5f * b.x) * cc.x;
        z4.y = a.y + __expf(0.5f * b.y) * cc.y;
        z4.z = a.z + __expf(0.5f * b.z) * cc.z;
        z4.w = a.w + __expf(0.5f * b.w) * cc.w;
        *(float4*)(zb + (pi * 16 + ri) * AST + col) = z4;
        uint2 hp = make_uint2(f2h2(z4.x, z4.y), f2h2(z4.z, z4.w));
        *(uint2*)(abuf + ((0 * 2 + pi) * 16 + ri) * ASTH + seg * 2) = hp;
        float slv = b.x + b.y + b.z + b.w;
        float se2 = cc.x*cc.x + cc.y*cc.y + cc.z*cc.z + cc.w*cc.w;
        #pragma unroll
        for (int m = 1; m <= 8; m <<= 1) {
            slv += __shfl_xor_sync(0xffffffffu, slv, m);
            se2 += __shfl_xor_sync(0xffffffffu, se2, m);
        }
        if (seg == 0 && v)
            out[(size_t)B * 64 + gr] = C_DENS - 0.5f * slv - 0.5f * se2;
    }

    // ---- Stage mats 4-7 (flow 1: needed by layers 0-3) BEFORE the sync.
    // Masks (d_h[h]=h%63+1): m_in: k<=n%63; m_hid: k%63<=n%63; m_out: k%63<n.
    #pragma unroll
    for (int it = 4; it < 8; ++it) {
        int i   = t + it * 512;
        int mat = i >> 9;
        int l   = mat & 3;
        int rem = i & 511;
        int kp  = rem >> 4;
        int n0  = (rem & 15) << 2;
        int k0  = kp << 1;
        int k1  = k0 + 1;
        int k1m = (k1 == 63) ? 0 : k1;
        float va[4] = {wa[it].x, wa[it].y, wa[it].z, wa[it].w};
        float vb[4] = {wb[it].x, wb[it].y, wb[it].z, wb[it].w};
        uint4 r;
        uint32_t* rp = &r.x;
        #pragma unroll
        for (int q = 0; q < 4; ++q) {
            int nn = n0 + q;
            int nm = (nn == 63) ? 0 : nn;
            bool ka = (l == 0) ? (k0 <= nm)
                    : (l == 3) ? (k0 < nn)
                               : (k0 <= nm);
            bool kb2 = (l == 0) ? (k1 <= nm)
                     : (l == 3) ? (k1m < nn)
                                : (k1m <= nm);
            rp[q] = f2h2(ka ? va[q] : 0.0f, kb2 ? vb[q] : 0.0f);
        }
        *(uint4*)(wsm2 + (mat * 32 + kp) * NSTW + n0) = r;
    }
    __syncthreads();

    // ---- Stage mats 0-3 (flow 0: first read at layer 4) AFTER the sync.
    // Overlaps layers 0-3; ordered before first use by layer 3's
    // __syncthreads below. Region disjoint from mats 4-7.
    #pragma unroll
    for (int it = 0; it < 4; ++it) {
        int i   = t + it * 512;
        int mat = i >> 9;
        int l   = mat & 3;
        int rem = i & 511;
        int kp  = rem >> 4;
        int n0  = (rem & 15) << 2;
        int k0  = kp << 1;
        int k1  = k0 + 1;
        int k1m = (k1 == 63) ? 0 : k1;
        float va[4] = {wa[it].x, wa[it].y, wa[it].z, wa[it].w};
        float vb[4] = {wb[it].x, wb[it].y, wb[it].z, wb[it].w};
        uint4 r;
        uint32_t* rp = &r.x;
        #pragma unroll
        for (int q = 0; q < 4; ++q) {
            int nn = n0 + q;
            int nm = (nn == 63) ? 0 : nn;
            bool ka = (l == 0) ? (k0 <= nm)
                    : (l == 3) ? (k0 < nn)
                               : (k0 <= nm);
            bool kb2 = (l == 0) ? (k1 <= nm)
                     : (l == 3) ? (k1m < nn)
                                : (k1m <= nm);
            rp[q] = f2h2(ka ? va[q] : 0.0f, kb2 ? vb[q] : 0.0f);
        }
        *(uint4*)(wsm2 + (mat * 32 + kp) * NSTW + n0) = r;
    }

    float* zrow0 = zb + (p * 16 + g) * AST;
    float* zrow1 = zb + (p * 16 + g + 8) * AST;

    // Prefetch layer-0 B-fragments (mat exec order: 4,5,6,7,0,1,2,3).
    uint32_t Bc0[4], Bc1[4], Bn0[4], Bn1[4];
    {
        const uint32_t* wbp = wsm2 + 4 * WMAT + n;
        #pragma unroll
        for (int kb = 0; kb < 4; ++kb) {
            Bc0[kb] = wbp[(kb * 8 + tig) * NSTW];
            Bc1[kb] = wbp[(kb * 8 + tig + 4) * NSTW];
        }
    }

    // ---- 8 chained layers, fully unrolled; tile-scoped barriers
    // (layer 3's barrier is block-wide to publish mats 0-3).
    #pragma unroll
    for (int li = 0; li < 8; ++li) {
        const int l  = ((li < 4) ? (4 + li) : (li - 4)) & 3;
        const int rd = li & 1, wr = (li + 1) & 1;

        // Prefetch next layer's B-fragments (conflict-free, overlaps MMAs).
        if (li < 7) {
            const int nmat = (li < 3) ? (5 + li) : (li - 3);
            const uint32_t* wbp = wsm2 + nmat * WMAT + n;
            #pragma unroll
            for (int kb = 0; kb < 4; ++kb) {
                Bn0[kb] = wbp[(kb * 8 + tig) * NSTW];
                Bn1[kb] = wbp[(kb * 8 + tig + 4) * NSTW];
            }
        }

        // A-fragments (conflict-free LDS; layer 4 = reversed swapped pairs).
        const uint32_t* ar0 = abuf + ((rd * 2 + p) * 16 + g) * ASTH;
        const uint32_t* ar1 = ar0 + 8 * ASTH;
        uint32_t A0[4], A1[4], A2[4], A3[4];
        #pragma unroll
        for (int kb = 0; kb < 4; ++kb) {
            if (li == 4) {
                int j0 = 31 - kb * 8 - tig, j2 = j0 - 4;
                A0[kb] = h2swap(ar0[j0]);
                A1[kb] = h2swap(ar1[j0]);
                A2[kb] = h2swap(ar0[j2]);
                A3[kb] = h2swap(ar1[j2]);
            } else {
                int j0 = kb * 8 + tig, j2 = j0 + 4;
                A0[kb] = ar0[j0];
                A1[kb] = ar1[j0];
                A2[kb] = ar0[j2];
                A3[kb] = ar1[j2];
            }
        }

        // 4 independent accumulator chains, tree-merged.
        float ac0[4] = {0.f, 0.f, 0.f, 0.f};
        float ac1[4] = {0.f, 0.f, 0.f, 0.f};
        float ac2[4] = {0.f, 0.f, 0.f, 0.f};
        float ac3[4] = {0.f, 0.f, 0.f, 0.f};
        mma16(ac0, A0[0], A1[0], A2[0], A3[0], Bc0[0], Bc1[0]);
        mma16(ac1, A0[1], A1[1], A2[1], A3[1], Bc0[1], Bc1[1]);
        mma16(ac2, A0[2], A1[2], A2[2], A3[2], Bc0[2], Bc1[2]);
        mma16(ac3, A0[3], A1[3], A2[3], A3[3], Bc0[3], Bc1[3]);
        float acc[4];
        #pragma unroll
        for (int i = 0; i < 4; ++i)
            acc[i] = (ac0[i] + ac1[i]) + (ac2[i] + ac3[i]);

        const float2 bias = biasr[li];
        uint32_t* aw0 = abuf + ((wr * 2 + p) * 16 + g) * ASTH;
        uint32_t* aw1 = aw0 + 8 * ASTH;
        const int jc = 4 * h + tig;           // half2 column of pair (c, c+1)

        if (l < 3) {
            float v0 = fmaxf(acc[0] + bias.x, 0.f);
            float v1 = fmaxf(acc[1] + bias.y, 0.f);
            float v2 = fmaxf(acc[2] + bias.x, 0.f);
            float v3 = fmaxf(acc[3] + bias.y, 0.f);
            aw0[jc] = f2h2(v0, v1);
            aw1[jc] = f2h2(v2, v3);
            tile_bar(p);
        } else if (li == 3) {
            // u = z - shift_1(z); exact fp32 to zb, fp16 to act buffer.
            float2 z0 = *(const float2*)(zrow0 + c);
            float2 z1 = *(const float2*)(zrow1 + c);
            float u0 = z0.x - (acc[0] + bias.x);
            float u1 = z0.y - (acc[1] + bias.y);
            float u2 = z1.x - (acc[2] + bias.x);
            float u3 = z1.y - (acc[3] + bias.y);
            aw0[jc] = f2h2(u0, u1);
            aw1[jc] = f2h2(u2, u3);
            *(float2*)(zrow0 + c) = make_float2(u0, u1);
            *(float2*)(zrow1 + c) = make_float2(u2, u3);
            __syncthreads();   // block-wide: also publishes mats 0-3 staging
        } else {
            // Final: out[c] = v[c] - shift_0(v)[c], v[c] = u[63-c] (fp32 zb).
            float2 zr0 = *(const float2*)(zrow0 + 62 - c);  // (u[62-c], u[63-c])
            float2 zr1 = *(const float2*)(zrow1 + 62 - c);
            float zn0 = zr0.y - (acc[0] + bias.x);
            float zn1 = zr0.x - (acc[1] + bias.y);
            float zn2 = zr1.y - (acc[2] + bias.x);
            float zn3 = zr1.x - (acc[3] + bias.y);
            const int r0 = rowbase + g, r1 = r0 + 8;
            if (r0 < B)
                *(float2*)(out + (size_t)r0*64 + c) = make_float2(zn0, zn1);
            if (r1 < B)
                *(float2*)(out + (size_t)r1*64 + c) = make_float2(zn2, zn3);
        }

        // Rotate prefetch buffers (register renames under full unroll).
        #pragma unroll
        for (int i = 0; i < 4; ++i) { Bc0[i] = Bn0[i]; Bc1[i] = Bn1[i]; }
    }
}

extern "C" void kernel_launch(void* const* d_in, const int* in_sizes, int n_in,
                              void* d_out, int out_size) {
    const float* zm = (const float*)d_in[0];
    const float* lv = (const float*)d_in[1];
    const float* ep = (const float*)d_in[2];
    const float* W0 = (const float*)d_in[3];
    const float* b0 = (const float*)d_in[4];
    const float* W1 = (const float*)d_in[5];
    const float* b1 = (const float*)d_in[6];
    const float* W2 = (const float*)d_in[7];
    const float* b2 = (const float*)d_in[8];
    const float* Wo = (const float*)d_in[9];
    const float* bo = (const float*)d_in[10];

    int B = in_sizes[0] / 64;

    int smem = (8 * WMAT + 2 * 2 * 16 * ASTH) * 4 + 2 * 16 * AST * 4;  // 91648
    cudaFuncSetAttribute(iaf_main, cudaFuncAttributeMaxDynamicSharedMemorySize,
                         smem);
    int grid = (B + 31) / 32;
    iaf_main<<<grid, 512, smem>>>(zm, lv, ep, W0, b0, W1, b1, W2, b2, Wo, bo,
                                  (float*)d_out, B);
}